// round 1
// baseline (speedup 1.0000x reference)
#include <cuda_runtime.h>
#include <cuda_bf16.h>
#include <math.h>

// ---------------- problem constants (from setup_inputs) ----------------
#define MAXN 100000
#define MAXE 1600000
#define MAXG 500
#define H 64
#define L 8
#define BN_EPS 1e-5f

// ---------------- device scratch (no allocs allowed) ----------------
__device__ float g_xs[(size_t)L * MAXN * H];   // per-layer node features (JK buffer)
__device__ float g_agg[(size_t)MAXN * H];      // aggregation scratch
__device__ float g_pooled[(size_t)MAXG * L * H];

// ---------------- f32x2 helpers ----------------
__device__ __forceinline__ unsigned long long pack2(float a, float b) {
    unsigned long long r;
    asm("mov.b64 %0, {%1, %2};" : "=l"(r) : "f"(a), "f"(b));
    return r;
}
__device__ __forceinline__ void unpack2(unsigned long long v, float& a, float& b) {
    asm("mov.b64 {%0, %1}, %2;" : "=f"(a), "=f"(b) : "l"(v));
}
__device__ __forceinline__ void fma2(unsigned long long& acc, unsigned long long a, unsigned long long b) {
    asm("fma.rn.f32x2 %0, %1, %2, %0;" : "+l"(acc) : "l"(a), "l"(b));
}

// GEMV: acc[32] (f32x2 pairs = 64 outputs) += z[0..63] * W[64x64] (row-major k x j)
// W in shared (warp-uniform broadcast loads), z in per-thread padded shared row.
__device__ __forceinline__ void gemv64(const float* __restrict__ Wsh,
                                       const float* __restrict__ zrow,
                                       unsigned long long acc[32]) {
#pragma unroll 4
    for (int k = 0; k < 64; ++k) {
        float zk = zrow[k];
        unsigned long long zz = pack2(zk, zk);
        const ulonglong2* wr = reinterpret_cast<const ulonglong2*>(Wsh + (k << 6));
#pragma unroll
        for (int q = 0; q < 16; ++q) {
            ulonglong2 w = wr[q];
            fma2(acc[2 * q],     zz, w.x);
            fma2(acc[2 * q + 1], zz, w.y);
        }
    }
}

// ---------------- edge aggregation kernels ----------------
// layer 0: scalar features
__global__ __launch_bounds__(256) void edge_agg1(const int* __restrict__ ei,
                                                 const float* __restrict__ x,
                                                 float* __restrict__ agg, int E) {
    int e = blockIdx.x * 256 + threadIdx.x;
    if (e >= E) return;
    int src = ei[e];
    int dst = ei[E + e];
    atomicAdd(&agg[dst], x[src]);
}

// layers 1..7: 64 features, 16 threads/edge, float4 gather + vector red
__global__ __launch_bounds__(256) void edge_agg64(const int* __restrict__ ei,
                                                  const float* __restrict__ h,
                                                  float* __restrict__ agg, int E) {
    int t = blockIdx.x * 256 + threadIdx.x;
    int e = t >> 4;
    if (e >= E) return;
    int q = t & 15;
    int src = ei[e];
    int dst = ei[E + e];
    float4 v = reinterpret_cast<const float4*>(h)[src * 16 + q];
    float4* ap = reinterpret_cast<float4*>(agg) + dst * 16 + q;
    asm volatile("red.global.add.v4.f32 [%0], {%1, %2, %3, %4};"
                 :: "l"(ap), "f"(v.x), "f"(v.y), "f"(v.z), "f"(v.w) : "memory");
}

// ---------------- node MLP kernels ----------------
// shared layout (generic layer): W1s[4096] | W2s[4096] | prm[384] | zs[128*65]
#define NODE_SMEM_FLOATS (4096 + 4096 + 384 + 128 * 65)
// layer 0: W2s[4096] | prm[384] | w1f[64] | zs[128*65]
#define NODE0_SMEM_FLOATS (4096 + 384 + 64 + 128 * 65)

__device__ __forceinline__ void load_bn_params(float* prm, int tid,
        const float* b1, const float* g1, const float* be1, const float* m1, const float* v1,
        const float* b2, const float* g2, const float* be2, const float* m2, const float* v2) {
    if (tid < 64) {
        float s1 = g1[tid] * rsqrtf(v1[tid] + BN_EPS);
        prm[tid]        = b1[tid];
        prm[64 + tid]   = s1;
        prm[128 + tid]  = fmaf(-m1[tid], s1, be1[tid]);
        float s2 = g2[tid] * rsqrtf(v2[tid] + BN_EPS);
        prm[192 + tid]  = b2[tid];
        prm[256 + tid]  = s2;
        prm[320 + tid]  = fmaf(-m2[tid], s2, be2[tid]);
    }
}

__global__ __launch_bounds__(128) void gin_node(
        const float* __restrict__ hprev, const float* __restrict__ agg,
        float* __restrict__ hout, const float* __restrict__ eps,
        const float* __restrict__ W1, const float* __restrict__ b1,
        const float* __restrict__ g1, const float* __restrict__ be1,
        const float* __restrict__ m1, const float* __restrict__ v1,
        const float* __restrict__ W2, const float* __restrict__ b2,
        const float* __restrict__ g2, const float* __restrict__ be2,
        const float* __restrict__ m2, const float* __restrict__ v2, int N) {
    extern __shared__ float sm[];
    float* W1s = sm;
    float* W2s = sm + 4096;
    float* prm = sm + 8192;
    float* zs  = sm + 8576;
    int tid = threadIdx.x;

    float4* w1d = reinterpret_cast<float4*>(W1s);
    float4* w2d = reinterpret_cast<float4*>(W2s);
    const float4* w1g = reinterpret_cast<const float4*>(W1);
    const float4* w2g = reinterpret_cast<const float4*>(W2);
#pragma unroll
    for (int i = tid; i < 1024; i += 128) { w1d[i] = w1g[i]; w2d[i] = w2g[i]; }
    load_bn_params(prm, tid, b1, g1, be1, m1, v1, b2, g2, be2, m2, v2);
    __syncthreads();

    int n = blockIdx.x * 128 + tid;
    if (n >= N) return;
    float ev = 1.0f + eps[0];
    float* zrow = zs + tid * 65;
    const float4* hp = reinterpret_cast<const float4*>(hprev) + n * 16;
    const float4* ap = reinterpret_cast<const float4*>(agg) + n * 16;
#pragma unroll
    for (int q = 0; q < 16; ++q) {
        float4 hv = hp[q];
        float4 av = ap[q];
        zrow[4 * q + 0] = fmaf(ev, hv.x, av.x);
        zrow[4 * q + 1] = fmaf(ev, hv.y, av.y);
        zrow[4 * q + 2] = fmaf(ev, hv.z, av.z);
        zrow[4 * q + 3] = fmaf(ev, hv.w, av.w);
    }

    unsigned long long acc[32];
#pragma unroll
    for (int i = 0; i < 32; ++i) acc[i] = 0ull;
    gemv64(W1s, zrow, acc);
#pragma unroll
    for (int j2 = 0; j2 < 32; ++j2) {
        float lo, hi;
        unpack2(acc[j2], lo, hi);
        int j = 2 * j2;
        zrow[j]     = fmaf(fmaxf(lo + prm[j], 0.f),     prm[64 + j],     prm[128 + j]);
        zrow[j + 1] = fmaf(fmaxf(hi + prm[j + 1], 0.f), prm[64 + j + 1], prm[128 + j + 1]);
        acc[j2] = 0ull;
    }
    gemv64(W2s, zrow, acc);
    float4* op = reinterpret_cast<float4*>(hout) + n * 16;
#pragma unroll
    for (int q = 0; q < 16; ++q) {
        float f0, f1, f2, f3;
        unpack2(acc[2 * q], f0, f1);
        unpack2(acc[2 * q + 1], f2, f3);
        int j = 4 * q;
        float4 o;
        o.x = fmaf(fmaxf(f0 + prm[192 + j],     0.f), prm[256 + j],     prm[320 + j]);
        o.y = fmaf(fmaxf(f1 + prm[192 + j + 1], 0.f), prm[256 + j + 1], prm[320 + j + 1]);
        o.z = fmaf(fmaxf(f2 + prm[192 + j + 2], 0.f), prm[256 + j + 2], prm[320 + j + 2]);
        o.w = fmaf(fmaxf(f3 + prm[192 + j + 3], 0.f), prm[256 + j + 3], prm[320 + j + 3]);
        op[q] = o;
    }
}

__global__ __launch_bounds__(128) void gin_node0(
        const float* __restrict__ x, const float* __restrict__ agg,
        float* __restrict__ hout, const float* __restrict__ eps,
        const float* __restrict__ W1f, const float* __restrict__ b1,
        const float* __restrict__ g1, const float* __restrict__ be1,
        const float* __restrict__ m1, const float* __restrict__ v1,
        const float* __restrict__ W2, const float* __restrict__ b2,
        const float* __restrict__ g2, const float* __restrict__ be2,
        const float* __restrict__ m2, const float* __restrict__ v2, int N) {
    extern __shared__ float sm[];
    float* W2s = sm;
    float* prm = sm + 4096;
    float* w1f = sm + 4480;
    float* zs  = sm + 4544;
    int tid = threadIdx.x;

    float4* w2d = reinterpret_cast<float4*>(W2s);
    const float4* w2g = reinterpret_cast<const float4*>(W2);
#pragma unroll
    for (int i = tid; i < 1024; i += 128) w2d[i] = w2g[i];
    if (tid < 64) w1f[tid] = W1f[tid];
    load_bn_params(prm, tid, b1, g1, be1, m1, v1, b2, g2, be2, m2, v2);
    __syncthreads();

    int n = blockIdx.x * 128 + tid;
    if (n >= N) return;
    float ev = 1.0f + eps[0];
    float z = fmaf(ev, x[n], agg[n]);
    float* zrow = zs + tid * 65;
#pragma unroll
    for (int j = 0; j < 64; ++j) {
        float y = fmaxf(fmaf(z, w1f[j], prm[j]), 0.f);
        zrow[j] = fmaf(y, prm[64 + j], prm[128 + j]);
    }
    unsigned long long acc[32];
#pragma unroll
    for (int i = 0; i < 32; ++i) acc[i] = 0ull;
    gemv64(W2s, zrow, acc);
    float4* op = reinterpret_cast<float4*>(hout) + n * 16;
#pragma unroll
    for (int q = 0; q < 16; ++q) {
        float f0, f1, f2, f3;
        unpack2(acc[2 * q], f0, f1);
        unpack2(acc[2 * q + 1], f2, f3);
        int j = 4 * q;
        float4 o;
        o.x = fmaf(fmaxf(f0 + prm[192 + j],     0.f), prm[256 + j],     prm[320 + j]);
        o.y = fmaf(fmaxf(f1 + prm[192 + j + 1], 0.f), prm[256 + j + 1], prm[320 + j + 1]);
        o.z = fmaf(fmaxf(f2 + prm[192 + j + 2], 0.f), prm[256 + j + 2], prm[320 + j + 2]);
        o.w = fmaf(fmaxf(f3 + prm[192 + j + 3], 0.f), prm[256 + j + 3], prm[320 + j + 3]);
        op[q] = o;
    }
}

// ---------------- pooling ----------------
__global__ __launch_bounds__(256) void pool_kernel(const int* __restrict__ batch,
                                                   const float* __restrict__ xs,
                                                   size_t layer_stride,
                                                   float* __restrict__ pooled, int N) {
    int t = blockIdx.x * 256 + threadIdx.x;
    int n = t >> 7;
    if (n >= N) return;
    int c = t & 127;           // float4 chunk within 512-wide jk row
    int l = c >> 4;
    int q = c & 15;
    float4 v = reinterpret_cast<const float4*>(xs + (size_t)l * layer_stride)[n * 16 + q];
    int g = batch[n];
    float4* pp = reinterpret_cast<float4*>(pooled) + (size_t)g * 128 + c;
    asm volatile("red.global.add.v4.f32 [%0], {%1, %2, %3, %4};"
                 :: "l"(pp), "f"(v.x), "f"(v.y), "f"(v.z), "f"(v.w) : "memory");
}

// ---------------- classifier head ----------------
__device__ __forceinline__ int lbound(const int* __restrict__ a, int n, int v) {
    int lo = 0, hi = n;
    while (lo < hi) {
        int mid = (lo + hi) >> 1;
        if (a[mid] < v) lo = mid + 1; else hi = mid;
    }
    return lo;
}

__global__ __launch_bounds__(64) void classify_kernel(
        const float* __restrict__ pooled, const int* __restrict__ batch, int N,
        const float* __restrict__ lw1, const float* __restrict__ lb1,
        const float* __restrict__ lw2, const float* __restrict__ lb2,
        float* __restrict__ out) {
    __shared__ float ps[512];
    __shared__ float hid[64];
    __shared__ float lg[3];
    __shared__ float inv;
    int g = blockIdx.x;
    int tid = threadIdx.x;
    if (tid == 0) {
        int a = lbound(batch, N, g);
        int b = lbound(batch, N, g + 1);
        int c = b - a;
        inv = 1.0f / (float)(c > 1 ? c : 1);
    }
    __syncthreads();
    for (int k = tid; k < 512; k += 64) ps[k] = pooled[(size_t)g * 512 + k] * inv;
    __syncthreads();
    float acc = lb1[tid];
#pragma unroll 8
    for (int k = 0; k < 512; ++k) acc = fmaf(ps[k], lw1[k * 64 + tid], acc);
    hid[tid] = fmaxf(acc, 0.f);
    __syncthreads();
    if (tid < 3) {
        float s = lb2[tid];
#pragma unroll
        for (int j = 0; j < 64; ++j) s = fmaf(hid[j], lw2[j * 3 + tid], s);
        lg[tid] = s;
    }
    __syncthreads();
    if (tid == 0) {
        float m = fmaxf(lg[0], fmaxf(lg[1], lg[2]));
        float e = expf(lg[0] - m) + expf(lg[1] - m) + expf(lg[2] - m);
        float lse = m + logf(e);
        out[g * 3 + 0] = lg[0] - lse;
        out[g * 3 + 1] = lg[1] - lse;
        out[g * 3 + 2] = lg[2] - lse;
    }
}

// ---------------- launcher ----------------
extern "C" void kernel_launch(void* const* d_in, const int* in_sizes, int n_in,
                              void* d_out, int out_size) {
    const float* x     = (const float*)d_in[0];
    const int*   ei    = (const int*)d_in[1];
    const int*   batch = (const int*)d_in[2];
    // num_graphs may or may not be materialized as a size-1 buffer
    int bi = (in_sizes[3] == 1) ? 4 : 3;
    const float* eps  = (const float*)d_in[bi + 0];
    const float* W1f  = (const float*)d_in[bi + 1];
    const float* W1r  = (const float*)d_in[bi + 2];
    const float* b1   = (const float*)d_in[bi + 3];
    const float* g1   = (const float*)d_in[bi + 4];
    const float* be1  = (const float*)d_in[bi + 5];
    const float* m1   = (const float*)d_in[bi + 6];
    const float* v1   = (const float*)d_in[bi + 7];
    const float* W2   = (const float*)d_in[bi + 8];
    const float* b2   = (const float*)d_in[bi + 9];
    const float* g2   = (const float*)d_in[bi + 10];
    const float* be2  = (const float*)d_in[bi + 11];
    const float* m2   = (const float*)d_in[bi + 12];
    const float* v2   = (const float*)d_in[bi + 13];
    const float* lw1  = (const float*)d_in[bi + 14];
    const float* lb1  = (const float*)d_in[bi + 15];
    const float* lw2  = (const float*)d_in[bi + 16];
    const float* lb2  = (const float*)d_in[bi + 17];

    int N = in_sizes[0];
    int E = in_sizes[1] / 2;
    int G = out_size / 3;
    if (N > MAXN) N = MAXN;
    if (E > MAXE) E = MAXE;
    if (G > MAXG) G = MAXG;
    size_t n64 = (size_t)N * 64;

    float *xs, *agg, *pooled;
    cudaGetSymbolAddress((void**)&xs, g_xs);
    cudaGetSymbolAddress((void**)&agg, g_agg);
    cudaGetSymbolAddress((void**)&pooled, g_pooled);

    static int smem_set = 0;
    cudaFuncSetAttribute(gin_node, cudaFuncAttributeMaxDynamicSharedMemorySize,
                         NODE_SMEM_FLOATS * 4);
    cudaFuncSetAttribute(gin_node0, cudaFuncAttributeMaxDynamicSharedMemorySize,
                         NODE0_SMEM_FLOATS * 4);
    (void)smem_set;

    int nodeGrid = (N + 127) / 128;

    // ----- layer 0 (scalar input) -----
    cudaMemsetAsync(agg, 0, (size_t)N * sizeof(float));
    edge_agg1<<<(E + 255) / 256, 256>>>(ei, x, agg, E);
    gin_node0<<<nodeGrid, 128, NODE0_SMEM_FLOATS * 4>>>(
        x, agg, xs, eps, W1f,
        b1, g1, be1, m1, v1,
        W2, b2, g2, be2, m2, v2, N);

    // ----- layers 1..7 -----
    for (int i = 1; i < L; ++i) {
        const float* hprev = xs + (size_t)(i - 1) * n64;
        float* hout = xs + (size_t)i * n64;
        cudaMemsetAsync(agg, 0, n64 * sizeof(float));
        edge_agg64<<<(E * 16 + 255) / 256, 256>>>(ei, hprev, agg, E);
        gin_node<<<nodeGrid, 128, NODE_SMEM_FLOATS * 4>>>(
            hprev, agg, hout, eps + i,
            W1r + (size_t)(i - 1) * 4096, b1 + i * 64,
            g1 + i * 64, be1 + i * 64, m1 + i * 64, v1 + i * 64,
            W2 + (size_t)i * 4096, b2 + i * 64,
            g2 + i * 64, be2 + i * 64, m2 + i * 64, v2 + i * 64, N);
    }

    // ----- pooling + head -----
    cudaMemsetAsync(pooled, 0, (size_t)G * 512 * sizeof(float));
    pool_kernel<<<((size_t)N * 128 + 255) / 256, 256>>>(batch, xs, n64, pooled, N);
    classify_kernel<<<G, 64>>>(pooled, batch, N, lw1, lb1, lw2, lb2, (float*)d_out);
}

// round 2
// speedup vs baseline: 1.8210x; 1.8210x over previous
#include <cuda_runtime.h>
#include <math.h>

#define MAXN 100000
#define MAXE 1600000
#define MAXG 500
#define LL 8
#define BN_EPS 1e-5f

// ---------------- device scratch ----------------
__device__ float g_h[2][(size_t)MAXN * 64];
__device__ float g_agg[(size_t)MAXN * 64];
__device__ float g_pooled[(size_t)MAXG * LL * 64];
__device__ int g_deg[MAXN + 1];
__device__ int g_off[MAXN + 2];
__device__ int g_pos[MAXN + 1];
__device__ int g_csr[MAXE];
__device__ int g_bsum[1024];

// ---------------- f32x2 helpers ----------------
__device__ __forceinline__ unsigned long long pack2(float a, float b) {
    unsigned long long r;
    asm("mov.b64 %0, {%1, %2};" : "=l"(r) : "f"(a), "f"(b));
    return r;
}
__device__ __forceinline__ void unpack2(unsigned long long v, float& a, float& b) {
    asm("mov.b64 {%0, %1}, %2;" : "=f"(a), "=f"(b) : "l"(v));
}
__device__ __forceinline__ void fma2(unsigned long long& acc, unsigned long long a, unsigned long long b) {
    asm("fma.rn.f32x2 %0, %1, %2, %0;" : "+l"(acc) : "l"(a), "l"(b));
}
__device__ __forceinline__ void red4(float4* p, float4 v) {
    asm volatile("red.global.add.v4.f32 [%0], {%1, %2, %3, %4};"
                 :: "l"(p), "f"(v.x), "f"(v.y), "f"(v.z), "f"(v.w) : "memory");
}

// ============ CSR build ============
__global__ __launch_bounds__(256) void deg_count(const int* __restrict__ ei, int E, int* __restrict__ deg) {
    int e = blockIdx.x * 256 + threadIdx.x;
    if (e >= E) return;
    atomicAdd(&deg[ei[E + e]], 1);
}

__global__ __launch_bounds__(512) void chunk_sum(const int* __restrict__ deg, int n, int* __restrict__ bsum) {
    __shared__ int sh[512];
    int t = threadIdx.x;
    int i = blockIdx.x * 512 + t;
    sh[t] = (i < n) ? deg[i] : 0;
    __syncthreads();
#pragma unroll
    for (int s = 256; s > 0; s >>= 1) {
        if (t < s) sh[t] += sh[t + s];
        __syncthreads();
    }
    if (t == 0) bsum[blockIdx.x] = sh[0];
}

__global__ __launch_bounds__(1024) void scan_bsum(int* __restrict__ bsum, int nb) {
    __shared__ int sh[1024];
    int t = threadIdx.x;
    int v = (t < nb) ? bsum[t] : 0;
    sh[t] = v;
    __syncthreads();
    for (int d = 1; d < 1024; d <<= 1) {
        int add = (t >= d) ? sh[t - d] : 0;
        __syncthreads();
        sh[t] += add;
        __syncthreads();
    }
    if (t < nb) bsum[t] = sh[t] - v;   // exclusive
}

__global__ __launch_bounds__(512) void chunk_scan(const int* __restrict__ deg, int n,
                                                  const int* __restrict__ bsum,
                                                  int* __restrict__ off, int* __restrict__ pos) {
    __shared__ int sh[512];
    int t = threadIdx.x;
    int i = blockIdx.x * 512 + t;
    int v = (i < n) ? deg[i] : 0;
    sh[t] = v;
    __syncthreads();
    for (int d = 1; d < 512; d <<= 1) {
        int add = (t >= d) ? sh[t - d] : 0;
        __syncthreads();
        sh[t] += add;
        __syncthreads();
    }
    if (i < n) {
        int ex = sh[t] - v + bsum[blockIdx.x];
        off[i] = ex;
        pos[i] = ex;
    }
}

__global__ __launch_bounds__(256) void csr_scatter(const int* __restrict__ ei, int E,
                                                   int* __restrict__ pos, int* __restrict__ csr) {
    int e = blockIdx.x * 256 + threadIdx.x;
    if (e >= E) return;
    int src = ei[e];
    int dst = ei[E + e];
    int p = atomicAdd(&pos[dst], 1);
    csr[p] = src;
}

// ============ CSR aggregation ============
// 64-wide features: 16 threads per node, float4 lanes, contiguous 256B row gather.
__global__ __launch_bounds__(256) void csr_agg64(const int* __restrict__ off, const int* __restrict__ csr,
                                                 const float* __restrict__ h, float* __restrict__ agg, int N) {
    int t = blockIdx.x * 256 + threadIdx.x;
    int n = t >> 4;
    if (n >= N) return;
    int q = t & 15;
    int b = off[n], e = off[n + 1];
    const float4* h4 = reinterpret_cast<const float4*>(h);
    float4 acc = make_float4(0.f, 0.f, 0.f, 0.f);
    for (int i = b; i < e; ++i) {
        int nb = __ldg(&csr[i]);
        float4 v = h4[nb * 16 + q];
        acc.x += v.x; acc.y += v.y; acc.z += v.z; acc.w += v.w;
    }
    reinterpret_cast<float4*>(agg)[n * 16 + q] = acc;
}

// scalar features (layer 0)
__global__ __launch_bounds__(256) void csr_agg1(const int* __restrict__ off, const int* __restrict__ csr,
                                                const float* __restrict__ x, float* __restrict__ agg, int N) {
    int n = blockIdx.x * 256 + threadIdx.x;
    if (n >= N) return;
    int b = off[n], e = off[n + 1];
    float s = 0.f;
    for (int i = b; i < e; ++i) s += x[__ldg(&csr[i])];
    agg[n] = s;
}

// ============ node MLP (register-tiled 8x8 GEMM) ============
// shared: W1s[4096] | W2s[4096] | prm[384] | zs[128*65]
#define NODE_SMEM_FLOATS (4096 + 4096 + 384 + 128 * 65)
#define NODE0_SMEM_FLOATS (4096 + 384 + 64 + 128 * 65)

__device__ __forceinline__ void load_bn_params(float* prm, int tid,
        const float* b1, const float* g1, const float* be1, const float* m1, const float* v1,
        const float* b2, const float* g2, const float* be2, const float* m2, const float* v2) {
    if (tid < 64) {
        float s1 = g1[tid] * rsqrtf(v1[tid] + BN_EPS);
        prm[tid]       = b1[tid];
        prm[64 + tid]  = s1;
        prm[128 + tid] = fmaf(-m1[tid], s1, be1[tid]);
        float s2 = g2[tid] * rsqrtf(v2[tid] + BN_EPS);
        prm[192 + tid] = b2[tid];
        prm[256 + tid] = s2;
        prm[320 + tid] = fmaf(-m2[tid], s2, be2[tid]);
    }
}

// acc[i][p]: node r*8+i, output pair (c*8+2p, c*8+2p+1)
__device__ __forceinline__ void gemm_tile(const float* __restrict__ Wsh,
                                          const float* __restrict__ zs,
                                          int r, int c, unsigned long long acc[8][4]) {
    const float* zbase = zs + r * 8 * 65;
    const float* wbase = Wsh + c * 8;
#pragma unroll 2
    for (int k = 0; k < 64; ++k) {
        unsigned long long zz[8];
#pragma unroll
        for (int i = 0; i < 8; ++i) {
            float z = zbase[i * 65 + k];
            zz[i] = pack2(z, z);
        }
        ulonglong2 wa = *reinterpret_cast<const ulonglong2*>(wbase + k * 64);
        ulonglong2 wb = *reinterpret_cast<const ulonglong2*>(wbase + k * 64 + 4);
#pragma unroll
        for (int i = 0; i < 8; ++i) {
            fma2(acc[i][0], zz[i], wa.x);
            fma2(acc[i][1], zz[i], wa.y);
            fma2(acc[i][2], zz[i], wb.x);
            fma2(acc[i][3], zz[i], wb.y);
        }
    }
}

// BN2 + write hout + RED pooled
__device__ __forceinline__ void epilogue(unsigned long long acc[8][4], const float* prm, int c,
                                         int n0, int r, int N, const int* sh_b,
                                         float* hout, float* pooled, int layer) {
    float4 b2a = *reinterpret_cast<const float4*>(prm + 192 + c * 8);
    float4 b2b = *reinterpret_cast<const float4*>(prm + 192 + c * 8 + 4);
    float4 s2a = *reinterpret_cast<const float4*>(prm + 256 + c * 8);
    float4 s2b = *reinterpret_cast<const float4*>(prm + 256 + c * 8 + 4);
    float4 t2a = *reinterpret_cast<const float4*>(prm + 320 + c * 8);
    float4 t2b = *reinterpret_cast<const float4*>(prm + 320 + c * 8 + 4);
#pragma unroll
    for (int i = 0; i < 8; ++i) {
        int node = r * 8 + i;
        int n = n0 + node;
        if (n >= N) break;
        float f0, f1, f2, f3, f4, f5, f6, f7;
        unpack2(acc[i][0], f0, f1);
        unpack2(acc[i][1], f2, f3);
        unpack2(acc[i][2], f4, f5);
        unpack2(acc[i][3], f6, f7);
        float4 oa, ob;
        oa.x = fmaf(fmaxf(f0 + b2a.x, 0.f), s2a.x, t2a.x);
        oa.y = fmaf(fmaxf(f1 + b2a.y, 0.f), s2a.y, t2a.y);
        oa.z = fmaf(fmaxf(f2 + b2a.z, 0.f), s2a.z, t2a.z);
        oa.w = fmaf(fmaxf(f3 + b2a.w, 0.f), s2a.w, t2a.w);
        ob.x = fmaf(fmaxf(f4 + b2b.x, 0.f), s2b.x, t2b.x);
        ob.y = fmaf(fmaxf(f5 + b2b.y, 0.f), s2b.y, t2b.y);
        ob.z = fmaf(fmaxf(f6 + b2b.z, 0.f), s2b.z, t2b.z);
        ob.w = fmaf(fmaxf(f7 + b2b.w, 0.f), s2b.w, t2b.w);
        float4* op = reinterpret_cast<float4*>(hout) + n * 16 + c * 2;
        op[0] = oa;
        op[1] = ob;
        int g = sh_b[node];
        float4* pp = reinterpret_cast<float4*>(pooled) + (size_t)g * 128 + layer * 16 + c * 2;
        red4(pp, oa);
        red4(pp + 1, ob);
    }
}

// BN1 applied to acc, written to zs as layer-2 input
__device__ __forceinline__ void mid_bn_store(unsigned long long acc[8][4], const float* prm, int c,
                                             int r, float* zs) {
    float4 b1a = *reinterpret_cast<const float4*>(prm + c * 8);
    float4 b1b = *reinterpret_cast<const float4*>(prm + c * 8 + 4);
    float4 s1a = *reinterpret_cast<const float4*>(prm + 64 + c * 8);
    float4 s1b = *reinterpret_cast<const float4*>(prm + 64 + c * 8 + 4);
    float4 t1a = *reinterpret_cast<const float4*>(prm + 128 + c * 8);
    float4 t1b = *reinterpret_cast<const float4*>(prm + 128 + c * 8 + 4);
#pragma unroll
    for (int i = 0; i < 8; ++i) {
        float* zr = zs + (r * 8 + i) * 65 + c * 8;
        float f0, f1, f2, f3, f4, f5, f6, f7;
        unpack2(acc[i][0], f0, f1);
        unpack2(acc[i][1], f2, f3);
        unpack2(acc[i][2], f4, f5);
        unpack2(acc[i][3], f6, f7);
        zr[0] = fmaf(fmaxf(f0 + b1a.x, 0.f), s1a.x, t1a.x);
        zr[1] = fmaf(fmaxf(f1 + b1a.y, 0.f), s1a.y, t1a.y);
        zr[2] = fmaf(fmaxf(f2 + b1a.z, 0.f), s1a.z, t1a.z);
        zr[3] = fmaf(fmaxf(f3 + b1a.w, 0.f), s1a.w, t1a.w);
        zr[4] = fmaf(fmaxf(f4 + b1b.x, 0.f), s1b.x, t1b.x);
        zr[5] = fmaf(fmaxf(f5 + b1b.y, 0.f), s1b.y, t1b.y);
        zr[6] = fmaf(fmaxf(f6 + b1b.z, 0.f), s1b.z, t1b.z);
        zr[7] = fmaf(fmaxf(f7 + b1b.w, 0.f), s1b.w, t1b.w);
    }
}

__global__ __launch_bounds__(128) void gin_node(
        const float* __restrict__ hprev, const float* __restrict__ agg,
        float* __restrict__ hout, const int* __restrict__ batch,
        float* __restrict__ pooled, int layer, const float* __restrict__ eps,
        const float* __restrict__ W1, const float* __restrict__ b1,
        const float* __restrict__ g1, const float* __restrict__ be1,
        const float* __restrict__ m1, const float* __restrict__ v1,
        const float* __restrict__ W2, const float* __restrict__ b2,
        const float* __restrict__ g2, const float* __restrict__ be2,
        const float* __restrict__ m2, const float* __restrict__ v2, int N) {
    extern __shared__ float sm[];
    float* W1s = sm;
    float* W2s = sm + 4096;
    float* prm = sm + 8192;
    float* zs  = sm + 8576;
    __shared__ int sh_b[128];
    int tid = threadIdx.x;

    float4* w1d = reinterpret_cast<float4*>(W1s);
    float4* w2d = reinterpret_cast<float4*>(W2s);
    const float4* w1g = reinterpret_cast<const float4*>(W1);
    const float4* w2g = reinterpret_cast<const float4*>(W2);
#pragma unroll
    for (int i = tid; i < 1024; i += 128) { w1d[i] = w1g[i]; w2d[i] = w2g[i]; }
    load_bn_params(prm, tid, b1, g1, be1, m1, v1, b2, g2, be2, m2, v2);

    int n0 = blockIdx.x * 128;
    int n = n0 + tid;
    float* zr = zs + tid * 65;
    if (n < N) {
        sh_b[tid] = batch[n];
        float ev = 1.0f + eps[0];
        const float4* hp = reinterpret_cast<const float4*>(hprev) + n * 16;
        const float4* ap = reinterpret_cast<const float4*>(agg) + n * 16;
#pragma unroll
        for (int q = 0; q < 16; ++q) {
            float4 hv = hp[q];
            float4 av = ap[q];
            zr[4 * q + 0] = fmaf(ev, hv.x, av.x);
            zr[4 * q + 1] = fmaf(ev, hv.y, av.y);
            zr[4 * q + 2] = fmaf(ev, hv.z, av.z);
            zr[4 * q + 3] = fmaf(ev, hv.w, av.w);
        }
    } else {
#pragma unroll
        for (int q = 0; q < 64; ++q) zr[q] = 0.f;
    }
    __syncthreads();

    int r = tid >> 3, c = tid & 7;
    unsigned long long acc[8][4];
#pragma unroll
    for (int i = 0; i < 8; ++i)
#pragma unroll
        for (int p = 0; p < 4; ++p) acc[i][p] = 0ull;

    gemm_tile(W1s, zs, r, c, acc);
    __syncthreads();
    mid_bn_store(acc, prm, c, r, zs);
#pragma unroll
    for (int i = 0; i < 8; ++i)
#pragma unroll
        for (int p = 0; p < 4; ++p) acc[i][p] = 0ull;
    __syncthreads();
    gemm_tile(W2s, zs, r, c, acc);
    epilogue(acc, prm, c, n0, r, N, sh_b, hout, pooled, layer);
}

__global__ __launch_bounds__(128) void gin_node0(
        const float* __restrict__ x, const float* __restrict__ agg,
        float* __restrict__ hout, const int* __restrict__ batch,
        float* __restrict__ pooled, const float* __restrict__ eps,
        const float* __restrict__ W1f, const float* __restrict__ b1,
        const float* __restrict__ g1, const float* __restrict__ be1,
        const float* __restrict__ m1, const float* __restrict__ v1,
        const float* __restrict__ W2, const float* __restrict__ b2,
        const float* __restrict__ g2, const float* __restrict__ be2,
        const float* __restrict__ m2, const float* __restrict__ v2, int N) {
    extern __shared__ float sm[];
    float* W2s = sm;
    float* prm = sm + 4096;
    float* w1f = sm + 4480;
    float* zs  = sm + 4544;
    __shared__ int sh_b[128];
    int tid = threadIdx.x;

    float4* w2d = reinterpret_cast<float4*>(W2s);
    const float4* w2g = reinterpret_cast<const float4*>(W2);
#pragma unroll
    for (int i = tid; i < 1024; i += 128) w2d[i] = w2g[i];
    if (tid < 64) w1f[tid] = W1f[tid];
    load_bn_params(prm, tid, b1, g1, be1, m1, v1, b2, g2, be2, m2, v2);
    __syncthreads();

    int n0 = blockIdx.x * 128;
    int n = n0 + tid;
    float* zr = zs + tid * 65;
    if (n < N) {
        sh_b[tid] = batch[n];
        float ev = 1.0f + eps[0];
        float z = fmaf(ev, x[n], agg[n]);
#pragma unroll
        for (int j = 0; j < 64; ++j) {
            float y = fmaxf(fmaf(z, w1f[j], prm[j]), 0.f);
            zr[j] = fmaf(y, prm[64 + j], prm[128 + j]);
        }
    } else {
#pragma unroll
        for (int j = 0; j < 64; ++j) zr[j] = 0.f;
    }
    __syncthreads();

    int r = tid >> 3, c = tid & 7;
    unsigned long long acc[8][4];
#pragma unroll
    for (int i = 0; i < 8; ++i)
#pragma unroll
        for (int p = 0; p < 4; ++p) acc[i][p] = 0ull;
    gemm_tile(W2s, zs, r, c, acc);
    epilogue(acc, prm, c, n0, r, N, sh_b, hout, pooled, 0);
}

// ---------------- classifier head ----------------
__device__ __forceinline__ int lbound(const int* __restrict__ a, int n, int v) {
    int lo = 0, hi = n;
    while (lo < hi) {
        int mid = (lo + hi) >> 1;
        if (a[mid] < v) lo = mid + 1; else hi = mid;
    }
    return lo;
}

__global__ __launch_bounds__(64) void classify_kernel(
        const float* __restrict__ pooled, const int* __restrict__ batch, int N,
        const float* __restrict__ lw1, const float* __restrict__ lb1,
        const float* __restrict__ lw2, const float* __restrict__ lb2,
        float* __restrict__ out) {
    __shared__ float ps[512];
    __shared__ float hid[64];
    __shared__ float lg[3];
    __shared__ float inv;
    int g = blockIdx.x;
    int tid = threadIdx.x;
    if (tid == 0) {
        int a = lbound(batch, N, g);
        int b = lbound(batch, N, g + 1);
        int c = b - a;
        inv = 1.0f / (float)(c > 1 ? c : 1);
    }
    __syncthreads();
    for (int k = tid; k < 512; k += 64) ps[k] = pooled[(size_t)g * 512 + k] * inv;
    __syncthreads();
    float acc = lb1[tid];
#pragma unroll 8
    for (int k = 0; k < 512; ++k) acc = fmaf(ps[k], lw1[k * 64 + tid], acc);
    hid[tid] = fmaxf(acc, 0.f);
    __syncthreads();
    if (tid < 3) {
        float s = lb2[tid];
#pragma unroll
        for (int j = 0; j < 64; ++j) s = fmaf(hid[j], lw2[j * 3 + tid], s);
        lg[tid] = s;
    }
    __syncthreads();
    if (tid == 0) {
        float m = fmaxf(lg[0], fmaxf(lg[1], lg[2]));
        float e = expf(lg[0] - m) + expf(lg[1] - m) + expf(lg[2] - m);
        float lse = m + logf(e);
        out[g * 3 + 0] = lg[0] - lse;
        out[g * 3 + 1] = lg[1] - lse;
        out[g * 3 + 2] = lg[2] - lse;
    }
}

// ---------------- launcher ----------------
extern "C" void kernel_launch(void* const* d_in, const int* in_sizes, int n_in,
                              void* d_out, int out_size) {
    const float* x     = (const float*)d_in[0];
    const int*   ei    = (const int*)d_in[1];
    const int*   batch = (const int*)d_in[2];
    int bi = (in_sizes[3] == 1) ? 4 : 3;
    const float* eps  = (const float*)d_in[bi + 0];
    const float* W1f  = (const float*)d_in[bi + 1];
    const float* W1r  = (const float*)d_in[bi + 2];
    const float* b1   = (const float*)d_in[bi + 3];
    const float* g1   = (const float*)d_in[bi + 4];
    const float* be1  = (const float*)d_in[bi + 5];
    const float* m1   = (const float*)d_in[bi + 6];
    const float* v1   = (const float*)d_in[bi + 7];
    const float* W2   = (const float*)d_in[bi + 8];
    const float* b2   = (const float*)d_in[bi + 9];
    const float* g2   = (const float*)d_in[bi + 10];
    const float* be2  = (const float*)d_in[bi + 11];
    const float* m2   = (const float*)d_in[bi + 12];
    const float* v2   = (const float*)d_in[bi + 13];
    const float* lw1  = (const float*)d_in[bi + 14];
    const float* lb1  = (const float*)d_in[bi + 15];
    const float* lw2  = (const float*)d_in[bi + 16];
    const float* lb2  = (const float*)d_in[bi + 17];

    int N = in_sizes[0];
    int E = in_sizes[1] / 2;
    int G = out_size / 3;
    if (N > MAXN) N = MAXN;
    if (E > MAXE) E = MAXE;
    if (G > MAXG) G = MAXG;
    size_t n64 = (size_t)N * 64;

    float *h0, *h1, *agg, *pooled;
    int *deg, *off, *pos, *csr, *bsum;
    cudaGetSymbolAddress((void**)&h0, g_h);
    h1 = h0 + (size_t)MAXN * 64;
    cudaGetSymbolAddress((void**)&agg, g_agg);
    cudaGetSymbolAddress((void**)&pooled, g_pooled);
    cudaGetSymbolAddress((void**)&deg, g_deg);
    cudaGetSymbolAddress((void**)&off, g_off);
    cudaGetSymbolAddress((void**)&pos, g_pos);
    cudaGetSymbolAddress((void**)&csr, g_csr);
    cudaGetSymbolAddress((void**)&bsum, g_bsum);

    cudaFuncSetAttribute(gin_node, cudaFuncAttributeMaxDynamicSharedMemorySize,
                         NODE_SMEM_FLOATS * 4);
    cudaFuncSetAttribute(gin_node0, cudaFuncAttributeMaxDynamicSharedMemorySize,
                         NODE0_SMEM_FLOATS * 4);

    int nodeGrid = (N + 127) / 128;
    int edgeGrid = (E + 255) / 256;
    int nScan = N + 1;
    int nb = (nScan + 511) / 512;

    // ----- CSR build (once per launch, reused by all layers) -----
    cudaMemsetAsync(deg, 0, (size_t)nScan * sizeof(int));
    cudaMemsetAsync(pooled, 0, (size_t)G * 512 * sizeof(float));
    deg_count<<<edgeGrid, 256>>>(ei, E, deg);
    chunk_sum<<<nb, 512>>>(deg, nScan, bsum);
    scan_bsum<<<1, 1024>>>(bsum, nb);
    chunk_scan<<<nb, 512>>>(deg, nScan, bsum, off, pos);
    csr_scatter<<<edgeGrid, 256>>>(ei, E, pos, csr);

    // ----- layer 0 (scalar input) -----
    csr_agg1<<<(N + 255) / 256, 256>>>(off, csr, x, agg, N);
    gin_node0<<<nodeGrid, 128, NODE0_SMEM_FLOATS * 4>>>(
        x, agg, h0, batch, pooled, eps, W1f,
        b1, g1, be1, m1, v1,
        W2, b2, g2, be2, m2, v2, N);

    // ----- layers 1..7 -----
    for (int i = 1; i < LL; ++i) {
        const float* hprev = (i & 1) ? h0 : h1;
        float* hout = (i & 1) ? h1 : h0;
        csr_agg64<<<((size_t)N * 16 + 255) / 256, 256>>>(off, csr, hprev, agg, N);
        gin_node<<<nodeGrid, 128, NODE_SMEM_FLOATS * 4>>>(
            hprev, agg, hout, batch, pooled, i, eps + i,
            W1r + (size_t)(i - 1) * 4096, b1 + i * 64,
            g1 + i * 64, be1 + i * 64, m1 + i * 64, v1 + i * 64,
            W2 + (size_t)i * 4096, b2 + i * 64,
            g2 + i * 64, be2 + i * 64, m2 + i * 64, v2 + i * 64, N);
    }

    // ----- head -----
    classify_kernel<<<G, 64>>>(pooled, batch, N, lw1, lb1, lw2, lb2, (float*)d_out);
}